// round 2
// baseline (speedup 1.0000x reference)
#include <cuda_runtime.h>
#include <math.h>

// ---------------- problem constants (match reference) ----------------
#define IN_DIM   128
#define E_DIM    32
#define CAT_DIM  160          // IN_DIM + E_DIM
#define OUT_DIM  128
#define TD       32
#define H_HEADS  8
#define HS       16
#define R_TYPES  8
#define T_TYPES  4
#define LN_EPS   1e-5f
#define E_MAX    100000
#define M_MAX    10000
#define TILE_E   64

// ---------------- device scratch (static, no allocation) ----------------
__device__ float    g_dia_s[(size_t)E_MAX * CAT_DIM];
__device__ float    g_dia_d[(size_t)E_MAX * IN_DIM];
__device__ float    g_q[(size_t)E_MAX * OUT_DIM];
__device__ float    g_k[(size_t)E_MAX * OUT_DIM];
__device__ float    g_v[(size_t)E_MAX * OUT_DIM];
__device__ float    g_a[(size_t)E_MAX * H_HEADS];
__device__ float    g_ex[(size_t)E_MAX * H_HEADS];
__device__ unsigned g_amax[(size_t)M_MAX * H_HEADS];
__device__ float    g_denom[(size_t)M_MAX * H_HEADS];
__device__ float    g_hacc[(size_t)M_MAX * OUT_DIM];
__device__ int      g_hist[R_TYPES];
__device__ int      g_off[R_TYPES];
__device__ int      g_cursor[R_TYPES];
__device__ int      g_order[E_MAX];

// ordered-uint mapping for float atomicMax
__device__ __forceinline__ unsigned fkey(float f) {
    unsigned u = __float_as_uint(f);
    return (u & 0x80000000u) ? ~u : (u | 0x80000000u);
}
__device__ __forceinline__ float finv(unsigned u) {
    u = (u & 0x80000000u) ? (u & 0x7fffffffu) : ~u;
    return __uint_as_float(u);
}

// ---------------- reset accumulators ----------------
__global__ void k_reset(int M) {
    int t = blockIdx.x * blockDim.x + threadIdx.x;
    if (t < M * OUT_DIM) g_hacc[t] = 0.f;
    if (t < M * H_HEADS) { g_amax[t] = 0u; g_denom[t] = 0.f; }
    if (t < R_TYPES)     { g_hist[t] = 0;  g_cursor[t] = 0; }
}

// ---------------- counting sort by etype ----------------
__global__ void k_hist(const int* __restrict__ etype, int E) {
    int e = blockIdx.x * blockDim.x + threadIdx.x;
    if (e < E) atomicAdd(&g_hist[etype[e]], 1);
}
__global__ void k_scan() {
    int s = 0;
    for (int r = 0; r < R_TYPES; r++) { g_off[r] = s; s += g_hist[r]; }
}
__global__ void k_scatter(const int* __restrict__ etype, int E) {
    int e = blockIdx.x * blockDim.x + threadIdx.x;
    if (e < E) {
        int r = etype[e];
        int p = atomicAdd(&g_cursor[r], 1);
        g_order[g_off[r] + p] = e;
    }
}

// ---------------- dia_s / dia_d: time encoding + LayerNorm (1 warp / edge) --
__global__ void k_dia(const float* __restrict__ src_h,
                      const float* __restrict__ src_tw,
                      const float* __restrict__ src_tb,
                      const float* __restrict__ edge_h,
                      const float* __restrict__ date,
                      const int*   __restrict__ src_idx,
                      const int*   __restrict__ dst_idx,
                      const float* __restrict__ sg, const float* __restrict__ sb,
                      const float* __restrict__ dg, const float* __restrict__ db,
                      int E)
{
    int warp = (blockIdx.x * blockDim.x + threadIdx.x) >> 5;
    int lane = threadIdx.x & 31;
    if (warp >= E) return;
    int e = warp;
    int s = src_idx[e];
    int d = dst_idx[e];
    float t = date[e];

    // -------- src side: 160 dims, 5 per lane --------
    float xs[5];
#pragma unroll
    for (int k = 0; k < 5; k++) {
        int j = lane + 32 * k;
        float v;
        if (j < TD)
            v = sinf(src_tw[(size_t)s * TD + j] * t + src_tb[(size_t)s * TD + j]) *
                src_h[(size_t)s * IN_DIM + j];
        else if (j < IN_DIM)
            v = src_h[(size_t)s * IN_DIM + j];
        else
            v = edge_h[(size_t)e * E_DIM + (j - IN_DIM)];
        xs[k] = v;
    }
    float sum = 0.f;
#pragma unroll
    for (int k = 0; k < 5; k++) sum += xs[k];
#pragma unroll
    for (int o = 16; o > 0; o >>= 1) sum += __shfl_xor_sync(0xffffffffu, sum, o);
    float mu = sum * (1.0f / CAT_DIM);
    float vs = 0.f;
#pragma unroll
    for (int k = 0; k < 5; k++) { float dd = xs[k] - mu; vs += dd * dd; }
#pragma unroll
    for (int o = 16; o > 0; o >>= 1) vs += __shfl_xor_sync(0xffffffffu, vs, o);
    float rstd = rsqrtf(vs * (1.0f / CAT_DIM) + LN_EPS);
#pragma unroll
    for (int k = 0; k < 5; k++) {
        int j = lane + 32 * k;
        g_dia_s[(size_t)e * CAT_DIM + j] = (xs[k] - mu) * rstd * sg[j] + sb[j];
    }

    // -------- dst side: 128 dims, 4 per lane --------
    float xd[4];
#pragma unroll
    for (int k = 0; k < 4; k++) {
        int j = lane + 32 * k;
        float v;
        if (j < TD)
            v = sinf(src_tw[(size_t)d * TD + j] * t + src_tb[(size_t)d * TD + j]) *
                src_h[(size_t)d * IN_DIM + j];
        else
            v = src_h[(size_t)d * IN_DIM + j];
        xd[k] = v;
    }
    float sum2 = 0.f;
#pragma unroll
    for (int k = 0; k < 4; k++) sum2 += xd[k];
#pragma unroll
    for (int o = 16; o > 0; o >>= 1) sum2 += __shfl_xor_sync(0xffffffffu, sum2, o);
    float mu2 = sum2 * (1.0f / IN_DIM);
    float vs2 = 0.f;
#pragma unroll
    for (int k = 0; k < 4; k++) { float dd = xd[k] - mu2; vs2 += dd * dd; }
#pragma unroll
    for (int o = 16; o > 0; o >>= 1) vs2 += __shfl_xor_sync(0xffffffffu, vs2, o);
    float rstd2 = rsqrtf(vs2 * (1.0f / IN_DIM) + LN_EPS);
#pragma unroll
    for (int k = 0; k < 4; k++) {
        int j = lane + 32 * k;
        g_dia_d[(size_t)e * IN_DIM + j] = (xd[k] - mu2) * rstd2 * dg[j] + db[j];
    }
}

// ---------------- typed Q/K/V projection: tiled GEMM, W in smem ----------
// WHICH: 0 = Q (dia_d, 128-in), 1 = K (dia_s, 160-in), 2 = V (dia_s, 160-in)
template <int IND, int WHICH>
__global__ void k_qkv(const float* __restrict__ Wfull, int E)
{
    const int r = blockIdx.y;
    const int cnt = g_hist[r];
    const int tbase = blockIdx.x * TILE_E;
    if (tbase >= cnt) return;
    const int base = g_off[r] + tbase;
    const int ne = min(TILE_E, cnt - tbase);

    const float* dia = (WHICH == 0) ? g_dia_d : g_dia_s;
    float* out = (WHICH == 0) ? g_q : (WHICH == 1) ? g_k : g_v;
    const float* W = Wfull + (size_t)r * IND * OUT_DIM;

    extern __shared__ float sm[];
    float* Ws = sm;                    // IND x 128
    float* Ds = sm + IND * OUT_DIM;    // IND x (TILE_E + 4)
    const int DS = TILE_E + 4;         // 68: 4-way write conflicts only
    __shared__ int so[TILE_E];

    if (threadIdx.x < TILE_E)
        so[threadIdx.x] = (threadIdx.x < ne) ? g_order[base + threadIdx.x] : 0;
    // load W (float4)
    for (int idx = threadIdx.x; idx < IND * (OUT_DIM / 4); idx += 256)
        ((float4*)Ws)[idx] = ((const float4*)W)[idx];
    __syncthreads();
    // load dia tile transposed
    for (int idx = threadIdx.x; idx < TILE_E * IND; idx += 256) {
        int e = idx / IND;
        int i = idx - e * IND;
        float v = 0.f;
        if (e < ne) v = dia[(size_t)so[e] * IND + i];
        Ds[i * DS + e] = v;
    }
    __syncthreads();

    const int c0 = (threadIdx.x & 31) * 4;   // column group (float4)
    const int e0 = (threadIdx.x >> 5) * 8;   // edge group of 8
    float acc[8][4];
#pragma unroll
    for (int a = 0; a < 8; a++)
#pragma unroll
        for (int b = 0; b < 4; b++) acc[a][b] = 0.f;

#pragma unroll 4
    for (int i = 0; i < IND; i++) {
        float4 w = *(const float4*)&Ws[i * OUT_DIM + c0];
        float4 d0 = *(const float4*)&Ds[i * DS + e0];
        float4 d1 = *(const float4*)&Ds[i * DS + e0 + 4];
        float de[8] = {d0.x, d0.y, d0.z, d0.w, d1.x, d1.y, d1.z, d1.w};
#pragma unroll
        for (int a = 0; a < 8; a++) {
            acc[a][0] += de[a] * w.x;
            acc[a][1] += de[a] * w.y;
            acc[a][2] += de[a] * w.z;
            acc[a][3] += de[a] * w.w;
        }
    }
#pragma unroll
    for (int a = 0; a < 8; a++) {
        int e = e0 + a;
        if (e < ne) {
            size_t ge = (size_t)so[e];
            float4 o = make_float4(acc[a][0], acc[a][1], acc[a][2], acc[a][3]);
            *(float4*)&out[ge * OUT_DIM + c0] = o;
        }
    }
}

// ---------------- attention logits + segment max ----------------
__global__ void k_attn_a(const int* __restrict__ dst_idx, int E)
{
    int t = blockIdx.x * blockDim.x + threadIdx.x;
    int e = t >> 3;
    int h = t & 7;
    if (e >= E) return;
    const float4* qp = (const float4*)&g_q[(size_t)e * OUT_DIM + h * HS];
    const float4* kp = (const float4*)&g_k[(size_t)e * OUT_DIM + h * HS];
    float a = 0.f;
#pragma unroll
    for (int i = 0; i < 4; i++) {
        float4 qv = qp[i], kv = kp[i];
        a += qv.x * kv.x + qv.y * kv.y + qv.z * kv.z + qv.w * kv.w;
    }
    a *= 0.08838834764831845f;  // 1/sqrt(128)
    g_a[(size_t)e * H_HEADS + h] = a;
    atomicMax(&g_amax[(size_t)dst_idx[e] * H_HEADS + h], fkey(a));
}

// ---------------- exp + segment denom ----------------
__global__ void k_attn_ex(const int* __restrict__ dst_idx, int E)
{
    int t = blockIdx.x * blockDim.x + threadIdx.x;
    int e = t >> 3;
    int h = t & 7;
    if (e >= E) return;
    int d = dst_idx[e];
    float am = finv(g_amax[(size_t)d * H_HEADS + h]);
    float ex = expf(g_a[(size_t)e * H_HEADS + h] - am);
    g_ex[(size_t)e * H_HEADS + h] = ex;
    atomicAdd(&g_denom[(size_t)d * H_HEADS + h], ex);
}

// ---------------- weighted-V aggregation ----------------
__global__ void k_agg(const int* __restrict__ dst_idx, int E)
{
    int t = blockIdx.x * blockDim.x + threadIdx.x;
    int e = t >> 7;
    int c = t & 127;
    if (e >= E) return;
    int d = dst_idx[e];
    int h = c >> 4;
    float alpha = g_ex[(size_t)e * H_HEADS + h] / g_denom[(size_t)d * H_HEADS + h];
    atomicAdd(&g_hacc[(size_t)d * OUT_DIM + c], g_v[(size_t)e * OUT_DIM + c] * alpha);
}

// ---------------- typed output projection + gated residual -------------
__global__ void k_out(const float* __restrict__ Wa,
                      const float* __restrict__ h_bias,
                      const float* __restrict__ skip,
                      const int*   __restrict__ ntype,
                      const float* __restrict__ src_h,
                      float* __restrict__ out, int M)
{
    int m = blockIdx.x;
    int c = threadIdx.x;
    __shared__ float sh[OUT_DIM];
    int r = ntype[m];
    sh[c] = g_hacc[(size_t)m * OUT_DIM + c] + h_bias[(size_t)r * OUT_DIM + c];
    __syncthreads();
    const float* W = Wa + (size_t)r * OUT_DIM * OUT_DIM;
    float acc = 0.f;
#pragma unroll 8
    for (int i = 0; i < OUT_DIM; i++)
        acc += sh[i] * W[i * OUT_DIM + c];
    float gate = 1.f / (1.f + expf(-skip[r]));
    out[(size_t)m * OUT_DIM + c] = acc * gate + src_h[(size_t)m * OUT_DIM + c] * (1.f - gate);
}

// ---------------- launch ----------------
extern "C" void kernel_launch(void* const* d_in, const int* in_sizes, int n_in,
                              void* d_out, int out_size)
{
    const float* src_h  = (const float*)d_in[0];
    const float* src_tw = (const float*)d_in[1];
    const float* src_tb = (const float*)d_in[2];
    const float* edge_h = (const float*)d_in[3];
    const float* date   = (const float*)d_in[4];
    const int*   src_idx = (const int*)d_in[5];
    const int*   dst_idx = (const int*)d_in[6];
    const int*   etype   = (const int*)d_in[7];
    const int*   ntype   = (const int*)d_in[8];
    const float* Wq = (const float*)d_in[9];
    const float* Wk = (const float*)d_in[10];
    const float* Wv = (const float*)d_in[11];
    const float* Wa = (const float*)d_in[12];
    const float* h_bias = (const float*)d_in[13];
    const float* skip   = (const float*)d_in[14];
    const float* sg = (const float*)d_in[15];
    const float* sb = (const float*)d_in[16];
    const float* dg = (const float*)d_in[17];
    const float* db = (const float*)d_in[18];
    float* out = (float*)d_out;

    const int E = in_sizes[4];   // date count
    const int M = in_sizes[8];   // ntype count

    // opt-in large dynamic smem (idempotent, capture-safe: not a stream op)
    const int SM160 = CAT_DIM * OUT_DIM * 4 + CAT_DIM * (TILE_E + 4) * 4;  // 125440
    const int SM128 = IN_DIM * OUT_DIM * 4 + IN_DIM * (TILE_E + 4) * 4;    // 100352
    cudaFuncSetAttribute(k_qkv<IN_DIM, 0>,  cudaFuncAttributeMaxDynamicSharedMemorySize, SM128);
    cudaFuncSetAttribute(k_qkv<CAT_DIM, 1>, cudaFuncAttributeMaxDynamicSharedMemorySize, SM160);
    cudaFuncSetAttribute(k_qkv<CAT_DIM, 2>, cudaFuncAttributeMaxDynamicSharedMemorySize, SM160);

    k_reset<<<(M * OUT_DIM + 255) / 256, 256>>>(M);
    k_hist<<<(E + 255) / 256, 256>>>(etype, E);
    k_scan<<<1, 1>>>();
    k_scatter<<<(E + 255) / 256, 256>>>(etype, E);
    k_dia<<<(E * 32 + 255) / 256, 256>>>(src_h, src_tw, src_tb, edge_h, date,
                                         src_idx, dst_idx, sg, sb, dg, db, E);
    dim3 gq((E + TILE_E - 1) / TILE_E, R_TYPES);
    k_qkv<IN_DIM, 0><<<gq, 256, SM128>>>(Wq, E);
    k_qkv<CAT_DIM, 1><<<gq, 256, SM160>>>(Wk, E);
    k_qkv<CAT_DIM, 2><<<gq, 256, SM160>>>(Wv, E);
    k_attn_a<<<(E * H_HEADS + 255) / 256, 256>>>(dst_idx, E);
    k_attn_ex<<<(E * H_HEADS + 255) / 256, 256>>>(dst_idx, E);
    k_agg<<<((size_t)E * OUT_DIM + 255) / 256, 256>>>(dst_idx, E);
    k_out<<<M, OUT_DIM>>>(Wa, h_bias, skip, ntype, src_h, out, M);
}

// round 3
// speedup vs baseline: 1.8288x; 1.8288x over previous
#include <cuda_runtime.h>
#include <math.h>

// ---------------- problem constants ----------------
#define IN_DIM   128
#define E_DIM    32
#define CAT_DIM  160
#define OUT_DIM  128
#define TD       32
#define H_HEADS  8
#define HS       16
#define R_TYPES  8
#define T_TYPES  4
#define LN_EPS   1e-5f
#define E_MAX    100000
#define M_MAX    10000
#define TILE_E   128
#define TILE_M   64

typedef unsigned long long ull;

// ---------------- device scratch ----------------
__device__ float    g_dia_s[(size_t)E_MAX * CAT_DIM];
__device__ float    g_dia_d[(size_t)E_MAX * IN_DIM];
__device__ float    g_q[(size_t)E_MAX * OUT_DIM];
__device__ float    g_k[(size_t)E_MAX * OUT_DIM];
__device__ float    g_v[(size_t)E_MAX * OUT_DIM];
__device__ float    g_a[(size_t)E_MAX * H_HEADS];
__device__ float    g_ex[(size_t)E_MAX * H_HEADS];
__device__ unsigned g_amax[(size_t)M_MAX * H_HEADS];
__device__ float    g_denom[(size_t)M_MAX * H_HEADS];
__device__ float    g_hacc[(size_t)M_MAX * OUT_DIM];
__device__ int      g_hist[R_TYPES], g_off[R_TYPES], g_cur[R_TYPES];
__device__ int      g_order[E_MAX];
__device__ int      g_nhist[T_TYPES], g_noff[T_TYPES], g_ncur[T_TYPES];
__device__ int      g_norder[M_MAX];

// ---------------- f32x2 packed-FMA helpers ----------------
__device__ __forceinline__ ull fma2(ull a, ull b, ull c) {
    ull d;
    asm("fma.rn.f32x2 %0, %1, %2, %3;" : "=l"(d) : "l"(a), "l"(b), "l"(c));
    return d;
}
__device__ __forceinline__ ull dup2(float x) {
    ull d; asm("mov.b64 %0, {%1, %1};" : "=l"(d) : "f"(x)); return d;
}
__device__ __forceinline__ float2 unpk(ull v) {
    float2 f; asm("mov.b64 {%0, %1}, %2;" : "=f"(f.x), "=f"(f.y) : "l"(v)); return f;
}

// ordered-uint mapping for float atomicMax
__device__ __forceinline__ unsigned fkey(float f) {
    unsigned u = __float_as_uint(f);
    return (u & 0x80000000u) ? ~u : (u | 0x80000000u);
}
__device__ __forceinline__ float finv(unsigned u) {
    u = (u & 0x80000000u) ? (u & 0x7fffffffu) : ~u;
    return __uint_as_float(u);
}

// ---------------- reset ----------------
__global__ void k_reset(int M) {
    int t = blockIdx.x * blockDim.x + threadIdx.x;
    if (t < M * OUT_DIM) g_hacc[t] = 0.f;
    if (t < M * H_HEADS) { g_amax[t] = 0u; g_denom[t] = 0.f; }
    if (t < R_TYPES)     { g_hist[t] = 0;  g_cur[t] = 0; }
    if (t < T_TYPES)     { g_nhist[t] = 0; g_ncur[t] = 0; }
}

// ---------------- warp-aggregated histograms (edges + nodes) -----------
__global__ void k_hist2(const int* __restrict__ etype, const int* __restrict__ ntype,
                        int E, int M) {
    int t = blockIdx.x * blockDim.x + threadIdx.x;
    int lane = threadIdx.x & 31;
    unsigned actE = __ballot_sync(0xffffffffu, t < E);
    if (t < E) {
        int r = etype[t];
        unsigned m = __match_any_sync(actE, r);
        if (lane == __ffs(m) - 1) atomicAdd(&g_hist[r], __popc(m));
    }
    unsigned actM = __ballot_sync(0xffffffffu, t < M);
    if (t < M) {
        int r = ntype[t];
        unsigned m = __match_any_sync(actM, r);
        if (lane == __ffs(m) - 1) atomicAdd(&g_nhist[r], __popc(m));
    }
}
__global__ void k_scan() {
    int s = 0;
    for (int r = 0; r < R_TYPES; r++) { g_off[r] = s; s += g_hist[r]; }
    s = 0;
    for (int r = 0; r < T_TYPES; r++) { g_noff[r] = s; s += g_nhist[r]; }
}
__global__ void k_scatter2(const int* __restrict__ etype, const int* __restrict__ ntype,
                           int E, int M) {
    int t = blockIdx.x * blockDim.x + threadIdx.x;
    int lane = threadIdx.x & 31;
    unsigned actE = __ballot_sync(0xffffffffu, t < E);
    if (t < E) {
        int r = etype[t];
        unsigned m = __match_any_sync(actE, r);
        int leader = __ffs(m) - 1;
        int rank = __popc(m & ((1u << lane) - 1));
        int base = 0;
        if (lane == leader) base = atomicAdd(&g_cur[r], __popc(m));
        base = __shfl_sync(actE, base, leader);
        g_order[g_off[r] + base + rank] = t;
    }
    unsigned actM = __ballot_sync(0xffffffffu, t < M);
    if (t < M) {
        int r = ntype[t];
        unsigned m = __match_any_sync(actM, r);
        int leader = __ffs(m) - 1;
        int rank = __popc(m & ((1u << lane) - 1));
        int base = 0;
        if (lane == leader) base = atomicAdd(&g_ncur[r], __popc(m));
        base = __shfl_sync(actM, base, leader);
        g_norder[g_noff[r] + base + rank] = t;
    }
}

// ---------------- time encoding + LayerNorm (1 warp / edge) ------------
__global__ void k_dia(const float* __restrict__ src_h,
                      const float* __restrict__ src_tw,
                      const float* __restrict__ src_tb,
                      const float* __restrict__ edge_h,
                      const float* __restrict__ date,
                      const int*   __restrict__ src_idx,
                      const int*   __restrict__ dst_idx,
                      const float* __restrict__ sg, const float* __restrict__ sb,
                      const float* __restrict__ dg, const float* __restrict__ db,
                      int E)
{
    int warp = (blockIdx.x * blockDim.x + threadIdx.x) >> 5;
    int lane = threadIdx.x & 31;
    if (warp >= E) return;
    int e = warp;
    int s = src_idx[e];
    int d = dst_idx[e];
    float t = date[e];

    float xs[5];
#pragma unroll
    for (int k = 0; k < 5; k++) {
        int j = lane + 32 * k;
        float v;
        if (j < TD)
            v = __sinf(src_tw[(size_t)s * TD + j] * t + src_tb[(size_t)s * TD + j]) *
                src_h[(size_t)s * IN_DIM + j];
        else if (j < IN_DIM)
            v = src_h[(size_t)s * IN_DIM + j];
        else
            v = edge_h[(size_t)e * E_DIM + (j - IN_DIM)];
        xs[k] = v;
    }
    float sum = 0.f;
#pragma unroll
    for (int k = 0; k < 5; k++) sum += xs[k];
#pragma unroll
    for (int o = 16; o > 0; o >>= 1) sum += __shfl_xor_sync(0xffffffffu, sum, o);
    float mu = sum * (1.0f / CAT_DIM);
    float vs = 0.f;
#pragma unroll
    for (int k = 0; k < 5; k++) { float dd = xs[k] - mu; vs += dd * dd; }
#pragma unroll
    for (int o = 16; o > 0; o >>= 1) vs += __shfl_xor_sync(0xffffffffu, vs, o);
    float rstd = rsqrtf(vs * (1.0f / CAT_DIM) + LN_EPS);
#pragma unroll
    for (int k = 0; k < 5; k++) {
        int j = lane + 32 * k;
        g_dia_s[(size_t)e * CAT_DIM + j] = (xs[k] - mu) * rstd * sg[j] + sb[j];
    }

    float xd[4];
#pragma unroll
    for (int k = 0; k < 4; k++) {
        int j = lane + 32 * k;
        float v;
        if (j < TD)
            v = __sinf(src_tw[(size_t)d * TD + j] * t + src_tb[(size_t)d * TD + j]) *
                src_h[(size_t)d * IN_DIM + j];
        else
            v = src_h[(size_t)d * IN_DIM + j];
        xd[k] = v;
    }
    float sum2 = 0.f;
#pragma unroll
    for (int k = 0; k < 4; k++) sum2 += xd[k];
#pragma unroll
    for (int o = 16; o > 0; o >>= 1) sum2 += __shfl_xor_sync(0xffffffffu, sum2, o);
    float mu2 = sum2 * (1.0f / IN_DIM);
    float vs2 = 0.f;
#pragma unroll
    for (int k = 0; k < 4; k++) { float dd = xd[k] - mu2; vs2 += dd * dd; }
#pragma unroll
    for (int o = 16; o > 0; o >>= 1) vs2 += __shfl_xor_sync(0xffffffffu, vs2, o);
    float rstd2 = rsqrtf(vs2 * (1.0f / IN_DIM) + LN_EPS);
#pragma unroll
    for (int k = 0; k < 4; k++) {
        int j = lane + 32 * k;
        g_dia_d[(size_t)e * IN_DIM + j] = (xd[k] - mu2) * rstd2 * dg[j] + db[j];
    }
}

// ---------------- typed projections: tiled GEMM with packed f32x2 ------
// KV=false: Q from dia_d (IND=128).  KV=true: K then V from dia_s (IND=160).
template <int IND, bool KV>
__global__ void __launch_bounds__(512, 1)
k_proj(const float* __restrict__ W1, const float* __restrict__ W2, int E)
{
    const int r = blockIdx.y;
    const int cnt = g_hist[r];
    const int tbase = blockIdx.x * TILE_E;
    if (tbase >= cnt) return;
    const int base = g_off[r] + tbase;
    const int ne = min(TILE_E, cnt - tbase);

    const float* dia = KV ? g_dia_s : g_dia_d;

    extern __shared__ float sm[];
    float* Ws = sm;                      // IND x 128
    float* Ds = sm + IND * OUT_DIM;      // IND x DS
    const int DS = TILE_E + 4;           // 132, keeps 16B alignment
    __shared__ int so[TILE_E];

    const int tid = threadIdx.x;  // 512
    if (tid < TILE_E) so[tid] = (tid < ne) ? g_order[base + tid] : 0;
    __syncthreads();

    // stage dia tile transposed
    for (int idx = tid; idx < TILE_E * IND; idx += 512) {
        int e = idx / IND;
        int i = idx - e * IND;
        Ds[i * DS + e] = (e < ne) ? dia[(size_t)so[e] * IND + i] : 0.f;
    }
    // stage W phase 0
    {
        const float* W = W1 + (size_t)r * IND * OUT_DIM;
        for (int idx = tid; idx < IND * (OUT_DIM / 4); idx += 512)
            ((float4*)Ws)[idx] = ((const float4*)W)[idx];
    }
    __syncthreads();

    const int c0 = (tid & 31) * 4;       // 4 output cols
    const int e0 = (tid >> 5) * 8;       // 8 edges (4 packed pairs)

#pragma unroll
    for (int phase = 0; phase < (KV ? 2 : 1); phase++) {
        ull acc[4][4];
#pragma unroll
        for (int p = 0; p < 4; p++)
#pragma unroll
            for (int b = 0; b < 4; b++) acc[p][b] = 0ull;

#pragma unroll 8
        for (int i = 0; i < IND; i++) {
            float4 w = *(const float4*)&Ws[i * OUT_DIM + c0];
            ull wd0 = dup2(w.x), wd1 = dup2(w.y), wd2 = dup2(w.z), wd3 = dup2(w.w);
            ulonglong2 p0 = *(const ulonglong2*)&Ds[i * DS + e0];
            ulonglong2 p1 = *(const ulonglong2*)&Ds[i * DS + e0 + 4];
            ull de[4] = {p0.x, p0.y, p1.x, p1.y};
#pragma unroll
            for (int p = 0; p < 4; p++) {
                acc[p][0] = fma2(de[p], wd0, acc[p][0]);
                acc[p][1] = fma2(de[p], wd1, acc[p][1]);
                acc[p][2] = fma2(de[p], wd2, acc[p][2]);
                acc[p][3] = fma2(de[p], wd3, acc[p][3]);
            }
        }

        float* outp = KV ? (phase == 0 ? g_k : g_v) : g_q;
#pragma unroll
        for (int p = 0; p < 4; p++) {
            float2 v0 = unpk(acc[p][0]);
            float2 v1 = unpk(acc[p][1]);
            float2 v2 = unpk(acc[p][2]);
            float2 v3 = unpk(acc[p][3]);
            int eA = e0 + 2 * p, eB = eA + 1;
            if (eA < ne)
                *(float4*)&outp[(size_t)so[eA] * OUT_DIM + c0] =
                    make_float4(v0.x, v1.x, v2.x, v3.x);
            if (eB < ne)
                *(float4*)&outp[(size_t)so[eB] * OUT_DIM + c0] =
                    make_float4(v0.y, v1.y, v2.y, v3.y);
        }

        if (KV && phase == 0) {
            __syncthreads();
            const float* W = W2 + (size_t)r * IND * OUT_DIM;
            for (int idx = tid; idx < IND * (OUT_DIM / 4); idx += 512)
                ((float4*)Ws)[idx] = ((const float4*)W)[idx];
            __syncthreads();
        }
    }
}

// ---------------- attention logits + segment max ----------------
__global__ void k_attn_a(const int* __restrict__ dst_idx, int E)
{
    int t = blockIdx.x * blockDim.x + threadIdx.x;
    int e = t >> 3;
    int h = t & 7;
    if (e >= E) return;
    const float4* qp = (const float4*)&g_q[(size_t)e * OUT_DIM + h * HS];
    const float4* kp = (const float4*)&g_k[(size_t)e * OUT_DIM + h * HS];
    float a = 0.f;
#pragma unroll
    for (int i = 0; i < 4; i++) {
        float4 qv = qp[i], kv = kp[i];
        a += qv.x * kv.x + qv.y * kv.y + qv.z * kv.z + qv.w * kv.w;
    }
    a *= 0.08838834764831845f;  // 1/sqrt(128)
    g_a[(size_t)e * H_HEADS + h] = a;
    atomicMax(&g_amax[(size_t)dst_idx[e] * H_HEADS + h], fkey(a));
}

// ---------------- exp + segment denom ----------------
__global__ void k_attn_ex(const int* __restrict__ dst_idx, int E)
{
    int t = blockIdx.x * blockDim.x + threadIdx.x;
    int e = t >> 3;
    int h = t & 7;
    if (e >= E) return;
    int d = dst_idx[e];
    float am = finv(g_amax[(size_t)d * H_HEADS + h]);
    float ex = __expf(g_a[(size_t)e * H_HEADS + h] - am);
    g_ex[(size_t)e * H_HEADS + h] = ex;
    atomicAdd(&g_denom[(size_t)d * H_HEADS + h], ex);
}

// ---------------- weighted-V aggregation (float4 per thread) -----------
__global__ void k_agg(const int* __restrict__ dst_idx, int E)
{
    int t = blockIdx.x * blockDim.x + threadIdx.x;
    int e = t >> 5;
    int c4 = t & 31;
    if (e >= E) return;
    int c0 = c4 * 4;
    int d = dst_idx[e];
    int h = c0 >> 4;
    float alpha = g_ex[(size_t)e * H_HEADS + h] / g_denom[(size_t)d * H_HEADS + h];
    float4 v = *(const float4*)&g_v[(size_t)e * OUT_DIM + c0];
    float* dst = &g_hacc[(size_t)d * OUT_DIM + c0];
    atomicAdd(dst + 0, v.x * alpha);
    atomicAdd(dst + 1, v.y * alpha);
    atomicAdd(dst + 2, v.z * alpha);
    atomicAdd(dst + 3, v.w * alpha);
}

// ---------------- typed output projection (tiled by ntype) -------------
__global__ void __launch_bounds__(256, 2)
k_out_t(const float* __restrict__ Wa,
        const float* __restrict__ h_bias,
        const float* __restrict__ skip,
        const float* __restrict__ src_h,
        float* __restrict__ out, int M)
{
    const int r = blockIdx.y;
    const int cnt = g_nhist[r];
    const int tbase = blockIdx.x * TILE_M;
    if (tbase >= cnt) return;
    const int base = g_noff[r] + tbase;
    const int ne = min(TILE_M, cnt - tbase);

    extern __shared__ float sm[];
    float* Ws = sm;                       // 128 x 128
    float* Ds = sm + OUT_DIM * OUT_DIM;   // 128 x 68
    const int DS = TILE_M + 4;
    __shared__ int no[TILE_M];

    const int tid = threadIdx.x;  // 256
    if (tid < TILE_M) no[tid] = (tid < ne) ? g_norder[base + tid] : 0;
    __syncthreads();

    {
        const float* W = Wa + (size_t)r * OUT_DIM * OUT_DIM;
        for (int idx = tid; idx < OUT_DIM * (OUT_DIM / 4); idx += 256)
            ((float4*)Ws)[idx] = ((const float4*)W)[idx];
    }
    for (int idx = tid; idx < TILE_M * OUT_DIM; idx += 256) {
        int m = idx >> 7;
        int i = idx & 127;
        Ds[i * DS + m] = (m < ne) ?
            g_hacc[(size_t)no[m] * OUT_DIM + i] + h_bias[(size_t)r * OUT_DIM + i] : 0.f;
    }
    __syncthreads();

    const int c0 = (tid & 31) * 4;
    const int m0 = (tid >> 5) * 8;
    ull acc[4][4];
#pragma unroll
    for (int p = 0; p < 4; p++)
#pragma unroll
        for (int b = 0; b < 4; b++) acc[p][b] = 0ull;

#pragma unroll 8
    for (int i = 0; i < OUT_DIM; i++) {
        float4 w = *(const float4*)&Ws[i * OUT_DIM + c0];
        ull wd0 = dup2(w.x), wd1 = dup2(w.y), wd2 = dup2(w.z), wd3 = dup2(w.w);
        ulonglong2 p0 = *(const ulonglong2*)&Ds[i * DS + m0];
        ulonglong2 p1 = *(const ulonglong2*)&Ds[i * DS + m0 + 4];
        ull de[4] = {p0.x, p0.y, p1.x, p1.y};
#pragma unroll
        for (int p = 0; p < 4; p++) {
            acc[p][0] = fma2(de[p], wd0, acc[p][0]);
            acc[p][1] = fma2(de[p], wd1, acc[p][1]);
            acc[p][2] = fma2(de[p], wd2, acc[p][2]);
            acc[p][3] = fma2(de[p], wd3, acc[p][3]);
        }
    }

    float gate = 1.f / (1.f + __expf(-skip[r]));
    float og = 1.f - gate;
#pragma unroll
    for (int p = 0; p < 4; p++) {
        float2 v0 = unpk(acc[p][0]);
        float2 v1 = unpk(acc[p][1]);
        float2 v2 = unpk(acc[p][2]);
        float2 v3 = unpk(acc[p][3]);
        int mA = m0 + 2 * p, mB = mA + 1;
        if (mA < ne) {
            size_t gm = (size_t)no[mA] * OUT_DIM + c0;
            float4 s = *(const float4*)&src_h[gm];
            *(float4*)&out[gm] = make_float4(v0.x * gate + s.x * og,
                                             v1.x * gate + s.y * og,
                                             v2.x * gate + s.z * og,
                                             v3.x * gate + s.w * og);
        }
        if (mB < ne) {
            size_t gm = (size_t)no[mB] * OUT_DIM + c0;
            float4 s = *(const float4*)&src_h[gm];
            *(float4*)&out[gm] = make_float4(v0.y * gate + s.x * og,
                                             v1.y * gate + s.y * og,
                                             v2.y * gate + s.z * og,
                                             v3.y * gate + s.w * og);
        }
    }
}

// ---------------- launch ----------------
extern "C" void kernel_launch(void* const* d_in, const int* in_sizes, int n_in,
                              void* d_out, int out_size)
{
    const float* src_h  = (const float*)d_in[0];
    const float* src_tw = (const float*)d_in[1];
    const float* src_tb = (const float*)d_in[2];
    const float* edge_h = (const float*)d_in[3];
    const float* date   = (const float*)d_in[4];
    const int*   src_idx = (const int*)d_in[5];
    const int*   dst_idx = (const int*)d_in[6];
    const int*   etype   = (const int*)d_in[7];
    const int*   ntype   = (const int*)d_in[8];
    const float* Wq = (const float*)d_in[9];
    const float* Wk = (const float*)d_in[10];
    const float* Wv = (const float*)d_in[11];
    const float* Wa = (const float*)d_in[12];
    const float* h_bias = (const float*)d_in[13];
    const float* skip   = (const float*)d_in[14];
    const float* sg = (const float*)d_in[15];
    const float* sb = (const float*)d_in[16];
    const float* dg = (const float*)d_in[17];
    const float* db = (const float*)d_in[18];
    float* out = (float*)d_out;

    const int E = in_sizes[4];
    const int M = in_sizes[8];

    const int SMQ  = (IN_DIM * OUT_DIM + IN_DIM * (TILE_E + 4)) * 4;    // 133120
    const int SMKV = (CAT_DIM * OUT_DIM + CAT_DIM * (TILE_E + 4)) * 4;  // 166400
    const int SMO  = (OUT_DIM * OUT_DIM + OUT_DIM * (TILE_M + 4)) * 4;  // 100352
    cudaFuncSetAttribute(k_proj<IN_DIM, false>, cudaFuncAttributeMaxDynamicSharedMemorySize, SMQ);
    cudaFuncSetAttribute(k_proj<CAT_DIM, true>, cudaFuncAttributeMaxDynamicSharedMemorySize, SMKV);
    cudaFuncSetAttribute(k_out_t, cudaFuncAttributeMaxDynamicSharedMemorySize, SMO);

    int mx = (E > M) ? E : M;
    k_reset<<<(M * OUT_DIM + 255) / 256, 256>>>(M);
    k_hist2<<<(mx + 255) / 256, 256>>>(etype, ntype, E, M);
    k_scan<<<1, 1>>>();
    k_scatter2<<<(mx + 255) / 256, 256>>>(etype, ntype, E, M);
    k_dia<<<(E * 32 + 255) / 256, 256>>>(src_h, src_tw, src_tb, edge_h, date,
                                         src_idx, dst_idx, sg, sb, dg, db, E);
    dim3 gq((E + TILE_E - 1) / TILE_E, R_TYPES);
    k_proj<IN_DIM,  false><<<gq, 512, SMQ >>>(Wq, nullptr, E);
    k_proj<CAT_DIM, true ><<<gq, 512, SMKV>>>(Wk, Wv, E);
    k_attn_a <<<(E * H_HEADS + 255) / 256, 256>>>(dst_idx, E);
    k_attn_ex<<<(E * H_HEADS + 255) / 256, 256>>>(dst_idx, E);
    k_agg<<<((size_t)E * 32 + 255) / 256, 256>>>(dst_idx, E);
    dim3 go((M + TILE_M - 1) / TILE_M, T_TYPES);
    k_out_t<<<go, 256, SMO>>>(Wa, h_bias, skip, src_h, out, M);
}

// round 9
// speedup vs baseline: 2.8435x; 1.5548x over previous
#include <cuda_runtime.h>
#include <cuda_bf16.h>
#include <math.h>
#include <stdint.h>

// ---------------- problem constants ----------------
#define IN_DIM   128
#define E_DIM    32
#define CAT_DIM  160
#define OUT_DIM  128
#define TD       32
#define H_HEADS  8
#define HS       16
#define R_TYPES  8
#define T_TYPES  4
#define LN_EPS   1e-5f
#define E_MAX    100000
#define M_MAX    10000
#define TILE_E   128
#define TILE_M   64

typedef unsigned long long ull;

// ---------------- device scratch ----------------
__device__ __nv_bfloat16 g_ds_hi[(size_t)E_MAX * CAT_DIM];
__device__ __nv_bfloat16 g_ds_lo[(size_t)E_MAX * CAT_DIM];
__device__ __nv_bfloat16 g_dd_hi[(size_t)E_MAX * IN_DIM];
__device__ __nv_bfloat16 g_dd_lo[(size_t)E_MAX * IN_DIM];
__device__ __nv_bfloat16 g_wq_hi[(size_t)R_TYPES * OUT_DIM * IN_DIM];
__device__ __nv_bfloat16 g_wq_lo[(size_t)R_TYPES * OUT_DIM * IN_DIM];
__device__ __nv_bfloat16 g_wk_hi[(size_t)R_TYPES * OUT_DIM * CAT_DIM];
__device__ __nv_bfloat16 g_wk_lo[(size_t)R_TYPES * OUT_DIM * CAT_DIM];
__device__ __nv_bfloat16 g_wv_hi[(size_t)R_TYPES * OUT_DIM * CAT_DIM];
__device__ __nv_bfloat16 g_wv_lo[(size_t)R_TYPES * OUT_DIM * CAT_DIM];

__device__ float    g_q[(size_t)E_MAX * OUT_DIM];
__device__ float    g_k[(size_t)E_MAX * OUT_DIM];
__device__ float    g_v[(size_t)E_MAX * OUT_DIM];
__device__ float    g_a[(size_t)E_MAX * H_HEADS];
__device__ float    g_ex[(size_t)E_MAX * H_HEADS];
__device__ unsigned g_amax[(size_t)M_MAX * H_HEADS];
__device__ float    g_denom[(size_t)M_MAX * H_HEADS];
__device__ float    g_hacc[(size_t)M_MAX * OUT_DIM];
__device__ int      g_hist[R_TYPES], g_off[R_TYPES], g_cur[R_TYPES];
__device__ int      g_order[E_MAX];
__device__ int      g_nhist[T_TYPES], g_noff[T_TYPES], g_ncur[T_TYPES];
__device__ int      g_norder[M_MAX];

// ---------------- f32x2 packed-FMA helpers (k_out) ----------------
__device__ __forceinline__ ull fma2(ull a, ull b, ull c) {
    ull d;
    asm("fma.rn.f32x2 %0, %1, %2, %3;" : "=l"(d) : "l"(a), "l"(b), "l"(c));
    return d;
}
__device__ __forceinline__ ull dup2(float x) {
    ull d; asm("mov.b64 %0, {%1, %1};" : "=l"(d) : "f"(x)); return d;
}
__device__ __forceinline__ float2 unpk(ull v) {
    float2 f; asm("mov.b64 {%0, %1}, %2;" : "=f"(f.x), "=f"(f.y) : "l"(v)); return f;
}

// ---------------- mma.sync helpers ----------------
__device__ __forceinline__ uint32_t smem_u32(const void* p) {
    uint32_t a;
    asm("{ .reg .u64 t; cvta.to.shared.u64 t, %1; cvt.u32.u64 %0, t; }"
        : "=r"(a) : "l"(p));
    return a;
}
__device__ __forceinline__ void ldsm4(uint32_t& r0, uint32_t& r1, uint32_t& r2,
                                      uint32_t& r3, uint32_t addr) {
    asm volatile("ldmatrix.sync.aligned.m8n8.x4.shared.b16 {%0,%1,%2,%3}, [%4];"
                 : "=r"(r0), "=r"(r1), "=r"(r2), "=r"(r3) : "r"(addr));
}
__device__ __forceinline__ void mma16816(float* d, uint32_t a0, uint32_t a1,
                                         uint32_t a2, uint32_t a3,
                                         uint32_t b0, uint32_t b1) {
    asm volatile(
        "mma.sync.aligned.m16n8k16.row.col.f32.bf16.bf16.f32 "
        "{%0,%1,%2,%3}, {%4,%5,%6,%7}, {%8,%9}, {%0,%1,%2,%3};"
        : "+f"(d[0]), "+f"(d[1]), "+f"(d[2]), "+f"(d[3])
        : "r"(a0), "r"(a1), "r"(a2), "r"(a3), "r"(b0), "r"(b1));
}

// ordered-uint mapping for float atomicMax
__device__ __forceinline__ unsigned fkey(float f) {
    unsigned u = __float_as_uint(f);
    return (u & 0x80000000u) ? ~u : (u | 0x80000000u);
}
__device__ __forceinline__ float finv(unsigned u) {
    u = (u & 0x80000000u) ? (u & 0x7fffffffu) : ~u;
    return __uint_as_float(u);
}

// ---------------- reset ----------------
__global__ void k_reset(int M) {
    int t = blockIdx.x * blockDim.x + threadIdx.x;
    if (t < M * OUT_DIM) g_hacc[t] = 0.f;
    if (t < M * H_HEADS) { g_amax[t] = 0u; g_denom[t] = 0.f; }
    if (t < R_TYPES)     { g_hist[t] = 0;  g_cur[t] = 0; }
    if (t < T_TYPES)     { g_nhist[t] = 0; g_ncur[t] = 0; }
}

// ---------------- warp-aggregated histograms ----------------
__global__ void k_hist2(const int* __restrict__ etype, const int* __restrict__ ntype,
                        int E, int M) {
    int t = blockIdx.x * blockDim.x + threadIdx.x;
    int lane = threadIdx.x & 31;
    unsigned actE = __ballot_sync(0xffffffffu, t < E);
    if (t < E) {
        int r = etype[t];
        unsigned m = __match_any_sync(actE, r);
        if (lane == __ffs(m) - 1) atomicAdd(&g_hist[r], __popc(m));
    }
    unsigned actM = __ballot_sync(0xffffffffu, t < M);
    if (t < M) {
        int r = ntype[t];
        unsigned m = __match_any_sync(actM, r);
        if (lane == __ffs(m) - 1) atomicAdd(&g_nhist[r], __popc(m));
    }
}
__global__ void k_scan() {
    int s = 0;
    for (int r = 0; r < R_TYPES; r++) { g_off[r] = s; s += g_hist[r]; }
    s = 0;
    for (int r = 0; r < T_TYPES; r++) { g_noff[r] = s; s += g_nhist[r]; }
}
__global__ void k_scatter2(const int* __restrict__ etype, const int* __restrict__ ntype,
                           int E, int M) {
    int t = blockIdx.x * blockDim.x + threadIdx.x;
    int lane = threadIdx.x & 31;
    unsigned actE = __ballot_sync(0xffffffffu, t < E);
    if (t < E) {
        int r = etype[t];
        unsigned m = __match_any_sync(actE, r);
        int leader = __ffs(m) - 1;
        int rank = __popc(m & ((1u << lane) - 1));
        int base = 0;
        if (lane == leader) base = atomicAdd(&g_cur[r], __popc(m));
        base = __shfl_sync(actE, base, leader);
        g_order[g_off[r] + base + rank] = t;
    }
    unsigned actM = __ballot_sync(0xffffffffu, t < M);
    if (t < M) {
        int r = ntype[t];
        unsigned m = __match_any_sync(actM, r);
        int leader = __ffs(m) - 1;
        int rank = __popc(m & ((1u << lane) - 1));
        int base = 0;
        if (lane == leader) base = atomicAdd(&g_ncur[r], __popc(m));
        base = __shfl_sync(actM, base, leader);
        g_norder[g_noff[r] + base + rank] = t;
    }
}

// ---------------- weight transpose + bf16 hi/lo split ----------------
__global__ void k_wconv(const float* __restrict__ Wq,
                        const float* __restrict__ Wk,
                        const float* __restrict__ Wv) {
    const int NQ = R_TYPES * OUT_DIM * IN_DIM;
    const int NKV = R_TYPES * OUT_DIM * CAT_DIM;
    int t = blockIdx.x * blockDim.x + threadIdx.x;
    float v; size_t dst;
    __nv_bfloat16 *ph, *pl;
    if (t < NQ) {
        int r = t / (OUT_DIM * IN_DIM), rem = t % (OUT_DIM * IN_DIM);
        int n = rem / IN_DIM, k = rem % IN_DIM;
        v = Wq[(size_t)r * IN_DIM * OUT_DIM + (size_t)k * OUT_DIM + n];
        dst = (size_t)r * OUT_DIM * IN_DIM + (size_t)n * IN_DIM + k;
        ph = g_wq_hi; pl = g_wq_lo;
    } else if (t < NQ + NKV) {
        int u = t - NQ;
        int r = u / (OUT_DIM * CAT_DIM), rem = u % (OUT_DIM * CAT_DIM);
        int n = rem / CAT_DIM, k = rem % CAT_DIM;
        v = Wk[(size_t)r * CAT_DIM * OUT_DIM + (size_t)k * OUT_DIM + n];
        dst = (size_t)r * OUT_DIM * CAT_DIM + (size_t)n * CAT_DIM + k;
        ph = g_wk_hi; pl = g_wk_lo;
    } else if (t < NQ + 2 * NKV) {
        int u = t - NQ - NKV;
        int r = u / (OUT_DIM * CAT_DIM), rem = u % (OUT_DIM * CAT_DIM);
        int n = rem / CAT_DIM, k = rem % CAT_DIM;
        v = Wv[(size_t)r * CAT_DIM * OUT_DIM + (size_t)k * OUT_DIM + n];
        dst = (size_t)r * OUT_DIM * CAT_DIM + (size_t)n * CAT_DIM + k;
        ph = g_wv_hi; pl = g_wv_lo;
    } else return;
    __nv_bfloat16 h = __float2bfloat16(v);
    ph[dst] = h;
    pl[dst] = __float2bfloat16(v - __bfloat162float(h));
}

// ---------------- time encoding + LayerNorm → bf16 hi/lo planes --------
__device__ __forceinline__ void split_store(__nv_bfloat16* ph, __nv_bfloat16* pl,
                                            size_t idx, float y) {
    __nv_bfloat16 h = __float2bfloat16(y);
    ph[idx] = h;
    pl[idx] = __float2bfloat16(y - __bfloat162float(h));
}

__global__ void k_dia(const float* __restrict__ src_h,
                      const float* __restrict__ src_tw,
                      const float* __restrict__ src_tb,
                      const float* __restrict__ edge_h,
                      const float* __restrict__ date,
                      const int*   __restrict__ src_idx,
                      const int*   __restrict__ dst_idx,
                      const float* __restrict__ sg, const float* __restrict__ sb,
                      const float* __restrict__ dg, const float* __restrict__ db,
                      int E)
{
    int warp = (blockIdx.x * blockDim.x + threadIdx.x) >> 5;
    int lane = threadIdx.x & 31;
    if (warp >= E) return;
    int e = warp;
    int s = src_idx[e];
    int d = dst_idx[e];
    float t = date[e];

    float xs[5];
#pragma unroll
    for (int k = 0; k < 5; k++) {
        int j = lane + 32 * k;
        float v;
        if (j < TD)
            v = __sinf(src_tw[(size_t)s * TD + j] * t + src_tb[(size_t)s * TD + j]) *
                src_h[(size_t)s * IN_DIM + j];
        else if (j < IN_DIM)
            v = src_h[(size_t)s * IN_DIM + j];
        else
            v = edge_h[(size_t)e * E_DIM + (j - IN_DIM)];
        xs[k] = v;
    }
    float sum = 0.f;
#pragma unroll
    for (int k = 0; k < 5; k++) sum += xs[k];
#pragma unroll
    for (int o = 16; o > 0; o >>= 1) sum += __shfl_xor_sync(0xffffffffu, sum, o);
    float mu = sum * (1.0f / CAT_DIM);
    float vs = 0.f;
#pragma unroll
    for (int k = 0; k < 5; k++) { float dd = xs[k] - mu; vs += dd * dd; }
#pragma unroll
    for (int o = 16; o > 0; o >>= 1) vs += __shfl_xor_sync(0xffffffffu, vs, o);
    float rstd = rsqrtf(vs * (1.0f / CAT_DIM) + LN_EPS);
#pragma unroll
    for (int k = 0; k < 5; k++) {
        int j = lane + 32 * k;
        float y = (xs[k] - mu) * rstd * sg[j] + sb[j];
        split_store(g_ds_hi, g_ds_lo, (size_t)e * CAT_DIM + j, y);
    }

    float xd[4];
#pragma unroll
    for (int k = 0; k < 4; k++) {
        int j = lane + 32 * k;
        float v;
        if (j < TD)
            v = __sinf(src_tw[(size_t)d * TD + j] * t + src_tb[(size_t)d * TD + j]) *
                src_h[(size_t)d * IN_DIM + j];
        else
            v = src_h[(size_t)d * IN_DIM + j];
        xd[k] = v;
    }
    float sum2 = 0.f;
#pragma unroll
    for (int k = 0; k < 4; k++) sum2 += xd[k];
#pragma unroll
    for (int o = 16; o > 0; o >>= 1) sum2 += __shfl_xor_sync(0xffffffffu, sum2, o);
    float mu2 = sum2 * (1.0f / IN_DIM);
    float vs2 = 0.f;
#pragma unroll
    for (int k = 0; k < 4; k++) { float dd = xd[k] - mu2; vs2 += dd * dd; }
#pragma unroll
    for (int o = 16; o > 0; o >>= 1) vs2 += __shfl_xor_sync(0xffffffffu, vs2, o);
    float rstd2 = rsqrtf(vs2 * (1.0f / IN_DIM) + LN_EPS);
#pragma unroll
    for (int k = 0; k < 4; k++) {
        int j = lane + 32 * k;
        float y = (xd[k] - mu2) * rstd2 * dg[j] + db[j];
        split_store(g_dd_hi, g_dd_lo, (size_t)e * IN_DIM + j, y);
    }
}

// ---------------- typed projections via mma.sync (split-bf16, 3 passes) ----
// KV=false: Q = dia_d @ Wq^T (KD=128). KV=true: K,V = dia_s @ Wk^T,Wv^T (KD=160).
// 512 threads, 16 warps. Warp w: edge stripe (w/2)*16, col half (w%2)*64.
template <int KD, bool KV>
__global__ void __launch_bounds__(512, 1)
k_pm()
{
    const int r = blockIdx.y;
    const int cnt = g_hist[r];
    const int tb = blockIdx.x * TILE_E;
    if (tb >= cnt) return;
    const int base = g_off[r] + tb;
    const int ne = min(TILE_E, cnt - tb);

    constexpr int SA  = KD + 8;     // padded row stride (bf16 elems)
    constexpr int SAB = SA * 2;     // bytes
    constexpr int NK  = KD / 16;
    constexpr int U   = KD / 8;     // uint4 chunks per row

    extern __shared__ __align__(16) char sm[];
    __nv_bfloat16* aH = (__nv_bfloat16*)sm;
    __nv_bfloat16* aL = aH + 128 * SA;
    __nv_bfloat16* bH = aL + 128 * SA;
    __nv_bfloat16* bL = bH + 128 * SA;
    __shared__ int so[TILE_E];

    const int tid = threadIdx.x, wid = tid >> 5, lane = tid & 31;
    if (tid < TILE_E) so[tid] = (tid < ne) ? g_order[base + tid] : 0;
    __syncthreads();

    // gather A tile (both planes)
    {
        const __nv_bfloat16* Ah = KV ? g_ds_hi : g_dd_hi;
        const __nv_bfloat16* Al = KV ? g_ds_lo : g_dd_lo;
        for (int idx = tid; idx < 128 * U; idx += 512) {
            int e = idx / U, u = idx - e * U;
            uint4 vh = make_uint4(0u, 0u, 0u, 0u), vl = vh;
            if (e < ne) {
                vh = ((const uint4*)(Ah + (size_t)so[e] * KD))[u];
                vl = ((const uint4*)(Al + (size_t)so[e] * KD))[u];
            }
            *(uint4*)((char*)aH + e * SAB + u * 16) = vh;
            *(uint4*)((char*)aL + e * SAB + u * 16) = vl;
        }
    }
    // stage B (first weight set)
    {
        const __nv_bfloat16* wh = (KV ? g_wk_hi : g_wq_hi) + (size_t)r * OUT_DIM * KD;
        const __nv_bfloat16* wl = (KV ? g_wk_lo : g_wq_lo) + (size_t)r * OUT_DIM * KD;
        for (int idx = tid; idx < 128 * U; idx += 512) {
            int n = idx / U, u = idx - n * U;
            *(uint4*)((char*)bH + n * SAB + u * 16) = ((const uint4*)(wh + (size_t)n * KD))[u];
            *(uint4*)((char*)bL + n * SAB + u * 16) = ((const uint4*)(wl + (size_t)n * KD))[u];
        }
    }
    __syncthreads();

    const int stripe = (wid >> 1) * 16;
    const int nhalf  = (wid & 1) * 64;

    // ldmatrix base offsets (byte addresses in shared space)
    const uint32_t aOffH = smem_u32(aH) + (uint32_t)(stripe + (lane & 15)) * SAB
                         + (uint32_t)(lane >> 4) * 16;
    const uint32_t aOffL = aOffH + (uint32_t)(128 * SAB);
    const int brow = ((lane >> 4) & 1) * 8 + (lane & 7);
    const int bko  = ((lane >> 3) & 1) * 16;
    const uint32_t bOffH = smem_u32(bH) + (uint32_t)(nhalf + brow) * SAB + bko;
    const uint32_t bOffL = bOffH + (uint32_t)(128 * SAB);

    float acc[8][4];
#pragma unroll
    for (int j = 0; j < 8; j++)
#pragma unroll
        for (int b = 0; b < 4; b++) acc[j][b] = 0.f;

    // one GEMM pass: acc += A(aOff) @ B(bOff)^T over KD
    auto run_pass = [&](uint32_t aOff, uint32_t bOff) {
#pragma unroll
        for (int ks = 0; ks < NK; ks++) {
            uint32_t a0, a1, a2, a3;
            ldsm4(a0, a1, a2, a3, aOff + ks * 32);
#pragma unroll
            for (int tp = 0; tp < 4; tp++) {
                uint32_t b0, b1, b2, b3;
                // non-trans: B smem is [n][k], pairs along k == col-major B frag
                ldsm4(b0, b1, b2, b3, bOff + tp * 16 * SAB + ks * 32);
                mma16816(acc[2 * tp],     a0, a1, a2, a3, b0, b1);
                mma16816(acc[2 * tp + 1], a0, a1, a2, a3, b2, b3);
            }
        }
    };
    // epilogue: acc -> global scatter
    auto wout = [&](float* outp) {
        int r0 = stripe + (lane >> 2);
        int c  = nhalf + (lane & 3) * 2;
        bool vA = r0 < ne, vB = (r0 + 8) < ne;
        size_t gA = vA ? (size_t)so[r0] * OUT_DIM : 0;
        size_t gB = vB ? (size_t)so[r0 + 8] * OUT_DIM : 0;
#pragma unroll
        for (int j = 0; j < 8; j++) {
            if (vA) *(float2*)&outp[gA + c + j * 8] = make_float2(acc[j][0], acc[j][1]);
            if (vB) *(float2*)&outp[gB + c + j * 8] = make_float2(acc[j][2], acc[j][3]);
        }
    };

    run_pass(aOffH, bOffH);   // hi * hi
    run_pass(aOffH, bOffL);   // hi * lo
    run_pass(aOffL, bOffH);   // lo * hi
    wout(KV ? g_k : g_q);

    if (KV) {
        __syncthreads();  // all warps done reading bH/bL
        {
            const __nv_bfloat16* wh = g_wv_hi + (size_t)r * OUT_DIM * KD;
            const __nv_bfloat16* wl = g_wv_lo + (size_t)r * OUT_DIM * KD;
            for (int idx = tid; idx < 128 * U; idx += 512) {
                int n = idx / U, u = idx - n * U;
                *(uint4*)((char*)bH + n * SAB + u * 16) = ((const uint4*)(wh + (size_t)n * KD))[u];
                *(uint4*)((char*)bL + n * SAB + u * 16) = ((const uint4*)(wl + (size_t)n * KD))[u];
            }
        }
        __syncthreads();
#pragma unroll
        for (int j = 0; j < 8; j++)
#pragma unroll
            for (int b = 0; b < 4; b++) acc[j][b] = 0.f;
        run_pass(aOffH, bOffH);
        run_pass(aOffH, bOffL);
        run_pass(aOffL, bOffH);
        wout(g_v);
    }
}

// ---------------- attention logits + segment max ----------------
__global__ void k_attn_a(const int* __restrict__ dst_idx, int E)
{
    int t = blockIdx.x * blockDim.x + threadIdx.x;
    int e = t >> 3;
    int h = t & 7;
    if (e >= E) return;
    const float4* qp = (const float4*)&g_q[(size_t)e * OUT_DIM + h * HS];
    const float4* kp = (const float4*)&g_k[(size_t)e * OUT_DIM + h * HS];
    float a = 0.f;
#pragma unroll
    for (int i = 0; i < 4; i++) {
        float4 qv = qp[i], kv = kp[i];
        a += qv.x * kv.x + qv.y * kv.y + qv.z * kv.z + qv.w * kv.w;
    }
    a *= 0.08838834764831845f;  // 1/sqrt(128)
    g_a[(size_t)e * H_HEADS + h] = a;
    atomicMax(&g_amax[(size_t)dst_idx[e] * H_HEADS + h], fkey(a));
}

// ---------------- exp + segment denom ----------------
__global__ void k_attn_ex(const int* __restrict__ dst_idx, int E)
{
    int t = blockIdx.x * blockDim.x + threadIdx.x;
    int e = t >> 3;
    int h = t & 7;
    if (e >= E) return;
    int d = dst_idx[e];
    float am = finv(g_amax[(size_t)d * H_HEADS + h]);
    float ex = __expf(g_a[(size_t)e * H_HEADS + h] - am);
    g_ex[(size_t)e * H_HEADS + h] = ex;
    atomicAdd(&g_denom[(size_t)d * H_HEADS + h], ex);
}

// ---------------- weighted-V aggregation ----------------
__global__ void k_agg(const int* __restrict__ dst_idx, int E)
{
    int t = blockIdx.x * blockDim.x + threadIdx.x;
    int e = t >> 5;
    int c4 = t & 31;
    if (e >= E) return;
    int c0 = c4 * 4;
    int d = dst_idx[e];
    int h = c0 >> 4;
    float alpha = g_ex[(size_t)e * H_HEADS + h] / g_denom[(size_t)d * H_HEADS + h];
    float4 v = *(const float4*)&g_v[(size_t)e * OUT_DIM + c0];
    float* dst = &g_hacc[(size_t)d * OUT_DIM + c0];
    atomicAdd(dst + 0, v.x * alpha);
    atomicAdd(dst + 1, v.y * alpha);
    atomicAdd(dst + 2, v.z * alpha);
    atomicAdd(dst + 3, v.w * alpha);
}

// ---------------- typed output projection (tiled by ntype) -------------
__global__ void __launch_bounds__(256, 2)
k_out_t(const float* __restrict__ Wa,
        const float* __restrict__ h_bias,
        const float* __restrict__ skip,
        const float* __restrict__ src_h,
        float* __restrict__ out, int M)
{
    const int r = blockIdx.y;
    const int cnt = g_nhist[r];
    const int tbase = blockIdx.x * TILE_M;
    if (tbase >= cnt) return;
    const int base = g_noff[r] + tbase;
    const int ne = min(TILE_M, cnt - tbase);

    extern __shared__ float smf[];
    float* Ws = smf;
    float* Ds = smf + OUT_DIM * OUT_DIM;
    const int DS = TILE_M + 4;
    __shared__ int no[TILE_M];

    const int tid = threadIdx.x;
    if (tid < TILE_M) no[tid] = (tid < ne) ? g_norder[base + tid] : 0;
    __syncthreads();

    {
        const float* W = Wa + (size_t)r * OUT_DIM * OUT_DIM;
        for (int idx = tid; idx < OUT_DIM * (OUT_DIM / 4); idx += 256)
            ((float4*)Ws)[idx] = ((const float4*)W)[idx];
    }
    for (int idx = tid; idx < TILE_M * OUT_DIM; idx += 256) {
        int m = idx >> 7;
        int i = idx & 127;
        Ds[i * DS + m] = (m < ne) ?
            g_hacc[(size_t)no[m] * OUT_DIM + i] + h_bias[(size_t)r * OUT_DIM + i] : 0.f;
    }
    __syncthreads();

    const int c0 = (tid & 31) * 4;
    const int m0 = (tid >> 5) * 8;
    ull acc[4][4];
#pragma unroll
    for (int p = 0; p < 4; p++)
#pragma unroll
        for (int b = 0; b < 4; b++) acc[p][b] = 0ull;

#pragma unroll 8
    for (int i = 0; i < OUT_DIM; i++) {
        float4 w = *(const float4*)&Ws[i * OUT_DIM + c0];
        ull wd0 = dup2(w.x), wd1 = dup2(w.y), wd2 = dup2(w.z), wd3 = dup2(w.w);
        ulonglong2 p0 = *(const ulonglong2*)&Ds[i * DS + m0];
        ulonglong2 p1 = *(const ulonglong2*)&Ds[i * DS + m0 + 4];
        ull de[4] = {p0.x, p0.y, p1.x, p1.y};
#pragma unroll
        for (int p = 0; p < 4; p++) {
            acc[p][0] = fma2(de[p], wd0, acc[p][0]);
            acc[p][1] = fma2(de[p], wd1, acc[p][1]);
            acc[p][2] = fma2(de[p], wd2, acc[p][2]);
            acc[p][3] = fma2(de[p], wd3, acc[p][3]);
        }
    }

    float gate = 1.f / (1.f + __expf(-skip[r]));
    float og = 1.f - gate;
#pragma unroll
    for (int p = 0; p < 4; p++) {
        float2 v0 = unpk(acc[p][0]);
        float2 v1 = unpk(acc[p][1]);
        float2 v2 = unpk(acc[p][2]);
        float2 v3 = unpk(acc[p][3]);
        int mA = m0 + 2 * p, mB = mA + 1;
        if (mA < ne) {
            size_t gm = (size_t)no[mA] * OUT_DIM + c0;
            float4 s = *(const float4*)&src_h[gm];
            *(float4*)&out[gm] = make_float4(v0.x * gate + s.x * og,
                                             v1.x * gate + s.y * og,
                                             v2.x * gate + s.z * og,
                                             v3.x * gate + s.w * og);
        }
        if (mB < ne) {
            size_t gm = (size_t)no[mB] * OUT_DIM + c0;
            float4 s = *(const float4*)&src_h[gm];
            *(float4*)&out[gm] = make_float4(v0.y * gate + s.x * og,
                                             v1.y * gate + s.y * og,
                                             v2.y * gate + s.z * og,
                                             v3.y * gate + s.w * og);
        }
    }
}

// ---------------- launch ----------------
extern "C" void kernel_launch(void* const* d_in, const int* in_sizes, int n_in,
                              void* d_out, int out_size)
{
    const float* src_h  = (const float*)d_in[0];
    const float* src_tw = (const float*)d_in[1];
    const float* src_tb = (const float*)d_in[2];
    const float* edge_h = (const float*)d_in[3];
    const float* date   = (const float*)d_in[4];
    const int*   src_idx = (const int*)d_in[5];
    const int*   dst_idx = (const int*)d_in[6];
    const int*   etype   = (const int*)d_in[7];
    const int*   ntype   = (const int*)d_in[8];
    const float* Wq = (const float*)d_in[9];
    const float* Wk = (const float*)d_in[10];
    const float* Wv = (const float*)d_in[11];
    const float* Wa = (const float*)d_in[12];
    const float* h_bias = (const float*)d_in[13];
    const float* skip   = (const float*)d_in[14];
    const float* sg = (const float*)d_in[15];
    const float* sb = (const float*)d_in[16];
    const float* dg = (const float*)d_in[17];
    const float* db = (const float*)d_in[18];
    float* out = (float*)d_out;

    const int E = in_sizes[4];
    const int M = in_sizes[8];

    const int SMQ  = 4 * 128 * (IN_DIM + 8) * 2;    // 139264
    const int SMKV = 4 * 128 * (CAT_DIM + 8) * 2;   // 172032
    const int SMO  = (OUT_DIM * OUT_DIM + OUT_DIM * (TILE_M + 4)) * 4;
    cudaFuncSetAttribute(k_pm<IN_DIM, false>, cudaFuncAttributeMaxDynamicSharedMemorySize, SMQ);
    cudaFuncSetAttribute(k_pm<CAT_DIM, true>, cudaFuncAttributeMaxDynamicSharedMemorySize, SMKV);
    cudaFuncSetAttribute(k_out_t, cudaFuncAttributeMaxDynamicSharedMemorySize, SMO);

    int mx = (E > M) ? E : M;
    k_reset<<<(M * OUT_DIM + 255) / 256, 256>>>(M);
    k_hist2<<<(mx + 255) / 256, 256>>>(etype, ntype, E, M);
    k_wconv<<<(R_TYPES * OUT_DIM * (IN_DIM + 2 * CAT_DIM) + 255) / 256, 256>>>(Wq, Wk, Wv);
    k_scan<<<1, 1>>>();
    k_scatter2<<<(mx + 255) / 256, 256>>>(etype, ntype, E, M);
    k_dia<<<(E * 32 + 255) / 256, 256>>>(src_h, src_tw, src_tb, edge_h, date,
                                         src_idx, dst_idx, sg, sb, dg, db, E);
    dim3 gq((E + TILE_E - 1) / TILE_E, R_TYPES);
    k_pm<IN_DIM,  false><<<gq, 512, SMQ >>>();
    k_pm<CAT_DIM, true ><<<gq, 512, SMKV>>>();
    k_attn_a <<<(E * H_HEADS + 255) / 256, 256>>>(dst_idx, E);
    k_attn_ex<<<(E * H_HEADS + 255) / 256, 256>>>(dst_idx, E);
    k_agg<<<((size_t)E * 32 + 255) / 256, 256>>>(dst_idx, E);
    dim3 go((M + TILE_M - 1) / TILE_M, T_TYPES);
    k_out_t<<<go, 256, SMO>>>(Wa, h_bias, skip, src_h, out, M);
}

// round 10
// speedup vs baseline: 2.9232x; 1.0280x over previous
#include <cuda_runtime.h>
#include <cuda_bf16.h>
#include <math.h>
#include <stdint.h>

// ---------------- problem constants ----------------
#define IN_DIM   128
#define E_DIM    32
#define CAT_DIM  160
#define OUT_DIM  128
#define TD       32
#define H_HEADS  8
#define HS       16
#define R_TYPES  8
#define T_TYPES  4
#define LN_EPS   1e-5f
#define E_MAX    100000
#define M_MAX    10000
#define TILE_E   128
#define TILE_M   64

typedef unsigned long long ull;

// ---------------- device scratch ----------------
__device__ __nv_bfloat16 g_ds_hi[(size_t)E_MAX * CAT_DIM];
__device__ __nv_bfloat16 g_ds_lo[(size_t)E_MAX * CAT_DIM];
__device__ __nv_bfloat16 g_dd_hi[(size_t)E_MAX * IN_DIM];
__device__ __nv_bfloat16 g_dd_lo[(size_t)E_MAX * IN_DIM];
__device__ __nv_bfloat16 g_wq_hi[(size_t)R_TYPES * OUT_DIM * IN_DIM];
__device__ __nv_bfloat16 g_wq_lo[(size_t)R_TYPES * OUT_DIM * IN_DIM];
__device__ __nv_bfloat16 g_wk_hi[(size_t)R_TYPES * OUT_DIM * CAT_DIM];
__device__ __nv_bfloat16 g_wk_lo[(size_t)R_TYPES * OUT_DIM * CAT_DIM];
__device__ __nv_bfloat16 g_wv_hi[(size_t)R_TYPES * OUT_DIM * CAT_DIM];
__device__ __nv_bfloat16 g_wv_lo[(size_t)R_TYPES * OUT_DIM * CAT_DIM];

__device__ float    g_q[(size_t)E_MAX * OUT_DIM];
__device__ float    g_k[(size_t)E_MAX * OUT_DIM];
__device__ float    g_v[(size_t)E_MAX * OUT_DIM];
__device__ float    g_a[(size_t)E_MAX * H_HEADS];
__device__ float    g_ex[(size_t)E_MAX * H_HEADS];
__device__ unsigned g_amax[(size_t)M_MAX * H_HEADS];
__device__ float    g_denom[(size_t)M_MAX * H_HEADS];
__device__ float    g_hacc[(size_t)M_MAX * OUT_DIM];

// fixed-stride type buckets (cursor == count after scatter)
__device__ int      g_cur[R_TYPES];
__device__ int      g_order[(size_t)R_TYPES * E_MAX];
__device__ int      g_ncur[T_TYPES];
__device__ int      g_norder[(size_t)T_TYPES * M_MAX];
// dst-sorted edge index (contiguous buckets)
__device__ int      g_dhist[M_MAX], g_doff[M_MAX], g_dcur[M_MAX];
__device__ int      g_dorder[E_MAX];

// ---------------- f32x2 packed-FMA helpers (k_out) ----------------
__device__ __forceinline__ ull fma2(ull a, ull b, ull c) {
    ull d;
    asm("fma.rn.f32x2 %0, %1, %2, %3;" : "=l"(d) : "l"(a), "l"(b), "l"(c));
    return d;
}
__device__ __forceinline__ ull dup2(float x) {
    ull d; asm("mov.b64 %0, {%1, %1};" : "=l"(d) : "f"(x)); return d;
}
__device__ __forceinline__ float2 unpk(ull v) {
    float2 f; asm("mov.b64 {%0, %1}, %2;" : "=f"(f.x), "=f"(f.y) : "l"(v)); return f;
}

// ---------------- mma.sync helpers ----------------
__device__ __forceinline__ uint32_t smem_u32(const void* p) {
    uint32_t a;
    asm("{ .reg .u64 t; cvta.to.shared.u64 t, %1; cvt.u32.u64 %0, t; }"
        : "=r"(a) : "l"(p));
    return a;
}
__device__ __forceinline__ void ldsm4(uint32_t& r0, uint32_t& r1, uint32_t& r2,
                                      uint32_t& r3, uint32_t addr) {
    asm volatile("ldmatrix.sync.aligned.m8n8.x4.shared.b16 {%0,%1,%2,%3}, [%4];"
                 : "=r"(r0), "=r"(r1), "=r"(r2), "=r"(r3) : "r"(addr));
}
__device__ __forceinline__ void mma16816(float* d, uint32_t a0, uint32_t a1,
                                         uint32_t a2, uint32_t a3,
                                         uint32_t b0, uint32_t b1) {
    asm volatile(
        "mma.sync.aligned.m16n8k16.row.col.f32.bf16.bf16.f32 "
        "{%0,%1,%2,%3}, {%4,%5,%6,%7}, {%8,%9}, {%0,%1,%2,%3};"
        : "+f"(d[0]), "+f"(d[1]), "+f"(d[2]), "+f"(d[3])
        : "r"(a0), "r"(a1), "r"(a2), "r"(a3), "r"(b0), "r"(b1));
}

// ordered-uint mapping for float atomicMax
__device__ __forceinline__ unsigned fkey(float f) {
    unsigned u = __float_as_uint(f);
    return (u & 0x80000000u) ? ~u : (u | 0x80000000u);
}
__device__ __forceinline__ float finv(unsigned u) {
    u = (u & 0x80000000u) ? (u & 0x7fffffffu) : ~u;
    return __uint_as_float(u);
}

// ---------------- reset ----------------
__global__ void k_reset(int M) {
    int t = blockIdx.x * blockDim.x + threadIdx.x;
    if (t < M * H_HEADS) { g_amax[t] = 0u; g_denom[t] = 0.f; }
    if (t < M)           { g_dhist[t] = 0; g_dcur[t] = 0; }
    if (t < R_TYPES)     g_cur[t] = 0;
    if (t < T_TYPES)     g_ncur[t] = 0;
}

// ---------------- scatter: etype buckets, ntype buckets, dst histogram ----
__global__ void k_scatter_all(const int* __restrict__ etype,
                              const int* __restrict__ ntype,
                              const int* __restrict__ dst_idx,
                              int E, int M) {
    int t = blockIdx.x * blockDim.x + threadIdx.x;
    int lane = threadIdx.x & 31;
    unsigned actE = __ballot_sync(0xffffffffu, t < E);
    if (t < E) {
        int r = etype[t];
        unsigned m = __match_any_sync(actE, r);
        int leader = __ffs(m) - 1;
        int rank = __popc(m & ((1u << lane) - 1));
        int base = 0;
        if (lane == leader) base = atomicAdd(&g_cur[r], __popc(m));
        base = __shfl_sync(actE, base, leader);
        g_order[(size_t)r * E_MAX + base + rank] = t;
        atomicAdd(&g_dhist[dst_idx[t]], 1);
    }
    unsigned actM = __ballot_sync(0xffffffffu, t < M);
    if (t < M) {
        int r = ntype[t];
        unsigned m = __match_any_sync(actM, r);
        int leader = __ffs(m) - 1;
        int rank = __popc(m & ((1u << lane) - 1));
        int base = 0;
        if (lane == leader) base = atomicAdd(&g_ncur[r], __popc(m));
        base = __shfl_sync(actM, base, leader);
        g_norder[(size_t)r * M_MAX + base + rank] = t;
    }
}

// ---------------- single-block exclusive scan of g_dhist -> g_doff -------
__global__ void __launch_bounds__(1024, 1) k_scan_dst(int M) {
    const int tid = threadIdx.x;
    const int per = (M + 1023) / 1024;
    const int start = tid * per;
    const int end = min(start + per, M);
    int local = 0;
    for (int i = start; i < end; i++) local += g_dhist[i];
    __shared__ int wsum[32];
    int lane = tid & 31, w = tid >> 5;
    int v = local;
#pragma unroll
    for (int o = 1; o < 32; o <<= 1) {
        int u = __shfl_up_sync(0xffffffffu, v, o);
        if (lane >= o) v += u;
    }
    if (lane == 31) wsum[w] = v;
    __syncthreads();
    if (w == 0) {
        int s = wsum[lane];
#pragma unroll
        for (int o = 1; o < 32; o <<= 1) {
            int u = __shfl_up_sync(0xffffffffu, s, o);
            if (lane >= o) s += u;
        }
        wsum[lane] = s;
    }
    __syncthreads();
    int run = v - local + (w > 0 ? wsum[w - 1] : 0);
    for (int i = start; i < end; i++) { g_doff[i] = run; run += g_dhist[i]; }
}

__global__ void k_scatter_dst(const int* __restrict__ dst_idx, int E) {
    int e = blockIdx.x * blockDim.x + threadIdx.x;
    if (e < E) {
        int d = dst_idx[e];
        int p = atomicAdd(&g_dcur[d], 1);
        g_dorder[g_doff[d] + p] = e;
    }
}

// ---------------- weight transpose (tiled smem) + bf16 hi/lo split -------
// in:  W[r][k][n] (n contiguous).  out: wh/wl[r][n][k] (k contiguous).
__global__ void k_wconv2(const float* __restrict__ Wq,
                         const float* __restrict__ Wk,
                         const float* __restrict__ Wv) {
    const int which = blockIdx.z;      // 0=Q, 1=K, 2=V
    const int r = blockIdx.y;
    const int KD = (which == 0) ? IN_DIM : CAT_DIM;
    const int ntiles_n = OUT_DIM / 32;
    const int tile = blockIdx.x;
    const int kt = tile / ntiles_n;    // k-tile
    const int nt = tile - kt * ntiles_n;
    if (kt * 32 >= KD) return;

    const float* W = (which == 0 ? Wq : which == 1 ? Wk : Wv)
                   + (size_t)r * KD * OUT_DIM;
    __nv_bfloat16* wh = (which == 0 ? g_wq_hi : which == 1 ? g_wk_hi : g_wv_hi)
                      + (size_t)r * OUT_DIM * KD;
    __nv_bfloat16* wl = (which == 0 ? g_wq_lo : which == 1 ? g_wk_lo : g_wv_lo)
                      + (size_t)r * OUT_DIM * KD;

    __shared__ float smt[32][33];
    const int tx = threadIdx.x, ty = threadIdx.y;  // 32 x 8
#pragma unroll
    for (int dy = 0; dy < 4; dy++) {
        int k = kt * 32 + ty + dy * 8;
        smt[ty + dy * 8][tx] = W[(size_t)k * OUT_DIM + nt * 32 + tx];
    }
    __syncthreads();
#pragma unroll
    for (int dy = 0; dy < 4; dy++) {
        int n = nt * 32 + ty + dy * 8;
        int k = kt * 32 + tx;
        float v = smt[tx][ty + dy * 8];
        __nv_bfloat16 h = __float2bfloat16(v);
        wh[(size_t)n * KD + k] = h;
        wl[(size_t)n * KD + k] = __float2bfloat16(v - __bfloat162float(h));
    }
}

// ---------------- time encoding + LayerNorm → bf16 hi/lo planes --------
__device__ __forceinline__ void split_store(__nv_bfloat16* ph, __nv_bfloat16* pl,
                                            size_t idx, float y) {
    __nv_bfloat16 h = __float2bfloat16(y);
    ph[idx] = h;
    pl[idx] = __float2bfloat16(y - __bfloat162float(h));
}

__global__ void k_dia(const float* __restrict__ src_h,
                      const float* __restrict__ src_tw,
                      const float* __restrict__ src_tb,
                      const float* __restrict__ edge_h,
                      const float* __restrict__ date,
                      const int*   __restrict__ src_idx,
                      const int*   __restrict__ dst_idx,
                      const float* __restrict__ sg, const float* __restrict__ sb,
                      const float* __restrict__ dg, const float* __restrict__ db,
                      int E)
{
    int warp = (blockIdx.x * blockDim.x + threadIdx.x) >> 5;
    int lane = threadIdx.x & 31;
    if (warp >= E) return;
    int e = warp;
    int s = src_idx[e];
    int d = dst_idx[e];
    float t = date[e];

    float xs[5];
#pragma unroll
    for (int k = 0; k < 5; k++) {
        int j = lane + 32 * k;
        float v;
        if (j < TD)
            v = __sinf(src_tw[(size_t)s * TD + j] * t + src_tb[(size_t)s * TD + j]) *
                src_h[(size_t)s * IN_DIM + j];
        else if (j < IN_DIM)
            v = src_h[(size_t)s * IN_DIM + j];
        else
            v = edge_h[(size_t)e * E_DIM + (j - IN_DIM)];
        xs[k] = v;
    }
    float sum = 0.f;
#pragma unroll
    for (int k = 0; k < 5; k++) sum += xs[k];
#pragma unroll
    for (int o = 16; o > 0; o >>= 1) sum += __shfl_xor_sync(0xffffffffu, sum, o);
    float mu = sum * (1.0f / CAT_DIM);
    float vs = 0.f;
#pragma unroll
    for (int k = 0; k < 5; k++) { float dd = xs[k] - mu; vs += dd * dd; }
#pragma unroll
    for (int o = 16; o > 0; o >>= 1) vs += __shfl_xor_sync(0xffffffffu, vs, o);
    float rstd = rsqrtf(vs * (1.0f / CAT_DIM) + LN_EPS);
#pragma unroll
    for (int k = 0; k < 5; k++) {
        int j = lane + 32 * k;
        float y = (xs[k] - mu) * rstd * sg[j] + sb[j];
        split_store(g_ds_hi, g_ds_lo, (size_t)e * CAT_DIM + j, y);
    }

    float xd[4];
#pragma unroll
    for (int k = 0; k < 4; k++) {
        int j = lane + 32 * k;
        float v;
        if (j < TD)
            v = __sinf(src_tw[(size_t)d * TD + j] * t + src_tb[(size_t)d * TD + j]) *
                src_h[(size_t)d * IN_DIM + j];
        else
            v = src_h[(size_t)d * IN_DIM + j];
        xd[k] = v;
    }
    float sum2 = 0.f;
#pragma unroll
    for (int k = 0; k < 4; k++) sum2 += xd[k];
#pragma unroll
    for (int o = 16; o > 0; o >>= 1) sum2 += __shfl_xor_sync(0xffffffffu, sum2, o);
    float mu2 = sum2 * (1.0f / IN_DIM);
    float vs2 = 0.f;
#pragma unroll
    for (int k = 0; k < 4; k++) { float dd = xd[k] - mu2; vs2 += dd * dd; }
#pragma unroll
    for (int o = 16; o > 0; o >>= 1) vs2 += __shfl_xor_sync(0xffffffffu, vs2, o);
    float rstd2 = rsqrtf(vs2 * (1.0f / IN_DIM) + LN_EPS);
#pragma unroll
    for (int k = 0; k < 4; k++) {
        int j = lane + 32 * k;
        float y = (xd[k] - mu2) * rstd2 * dg[j] + db[j];
        split_store(g_dd_hi, g_dd_lo, (size_t)e * IN_DIM + j, y);
    }
}

// ---------------- typed projections via mma.sync (split-bf16, 3 passes) ----
template <int KD, bool KV>
__global__ void __launch_bounds__(512, 1)
k_pm()
{
    const int r = blockIdx.y;
    const int cnt = g_cur[r];
    const int tb = blockIdx.x * TILE_E;
    if (tb >= cnt) return;
    const size_t base = (size_t)r * E_MAX + tb;
    const int ne = min(TILE_E, cnt - tb);

    constexpr int SA  = KD + 8;
    constexpr int SAB = SA * 2;
    constexpr int NK  = KD / 16;
    constexpr int U   = KD / 8;

    extern __shared__ __align__(16) char sm[];
    __nv_bfloat16* aH = (__nv_bfloat16*)sm;
    __nv_bfloat16* aL = aH + 128 * SA;
    __nv_bfloat16* bH = aL + 128 * SA;
    __nv_bfloat16* bL = bH + 128 * SA;
    __shared__ int so[TILE_E];

    const int tid = threadIdx.x, wid = tid >> 5, lane = tid & 31;
    if (tid < TILE_E) so[tid] = (tid < ne) ? g_order[base + tid] : 0;
    __syncthreads();

    {
        const __nv_bfloat16* Ah = KV ? g_ds_hi : g_dd_hi;
        const __nv_bfloat16* Al = KV ? g_ds_lo : g_dd_lo;
        for (int idx = tid; idx < 128 * U; idx += 512) {
            int e = idx / U, u = idx - e * U;
            uint4 vh = make_uint4(0u, 0u, 0u, 0u), vl = vh;
            if (e < ne) {
                vh = ((const uint4*)(Ah + (size_t)so[e] * KD))[u];
                vl = ((const uint4*)(Al + (size_t)so[e] * KD))[u];
            }
            *(uint4*)((char*)aH + e * SAB + u * 16) = vh;
            *(uint4*)((char*)aL + e * SAB + u * 16) = vl;
        }
    }
    {
        const __nv_bfloat16* wh = (KV ? g_wk_hi : g_wq_hi) + (size_t)r * OUT_DIM * KD;
        const __nv_bfloat16* wl = (KV ? g_wk_lo : g_wq_lo) + (size_t)r * OUT_DIM * KD;
        for (int idx = tid; idx < 128 * U; idx += 512) {
            int n = idx / U, u = idx - n * U;
            *(uint4*)((char*)bH + n * SAB + u * 16) = ((const uint4*)(wh + (size_t)n * KD))[u];
            *(uint4*)((char*)bL + n * SAB + u * 16) = ((const uint4*)(wl + (size_t)n * KD))[u];
        }
    }
    __syncthreads();

    const int stripe = (wid >> 1) * 16;
    const int nhalf  = (wid & 1) * 64;

    const uint32_t aOffH = smem_u32(aH) + (uint32_t)(stripe + (lane & 15)) * SAB
                         + (uint32_t)(lane >> 4) * 16;
    const uint32_t aOffL = aOffH + (uint32_t)(128 * SAB);
    const int brow = ((lane >> 4) & 1) * 8 + (lane & 7);
    const int bko  = ((lane >> 3) & 1) * 16;
    const uint32_t bOffH = smem_u32(bH) + (uint32_t)(nhalf + brow) * SAB + bko;
    const uint32_t bOffL = bOffH + (uint32_t)(128 * SAB);

    float acc[8][4];
#pragma unroll
    for (int j = 0; j < 8; j++)
#pragma unroll
        for (int b = 0; b < 4; b++) acc[j][b] = 0.f;

    auto run_pass = [&](uint32_t aOff, uint32_t bOff) {
#pragma unroll
        for (int ks = 0; ks < NK; ks++) {
            uint32_t a0, a1, a2, a3;
            ldsm4(a0, a1, a2, a3, aOff + ks * 32);
#pragma unroll
            for (int tp = 0; tp < 4; tp++) {
                uint32_t b0, b1, b2, b3;
                ldsm4(b0, b1, b2, b3, bOff + tp * 16 * SAB + ks * 32);
                mma16816(acc[2 * tp],     a0, a1, a2, a3, b0, b1);
                mma16816(acc[2 * tp + 1], a0, a1, a2, a3, b2, b3);
            }
        }
    };
    auto wout = [&](float* outp) {
        int r0 = stripe + (lane >> 2);
        int c  = nhalf + (lane & 3) * 2;
        bool vA = r0 < ne, vB = (r0 + 8) < ne;
        size_t gA = vA ? (size_t)so[r0] * OUT_DIM : 0;
        size_t gB = vB ? (size_t)so[r0 + 8] * OUT_DIM : 0;
#pragma unroll
        for (int j = 0; j < 8; j++) {
            if (vA) *(float2*)&outp[gA + c + j * 8] = make_float2(acc[j][0], acc[j][1]);
            if (vB) *(float2*)&outp[gB + c + j * 8] = make_float2(acc[j][2], acc[j][3]);
        }
    };

    run_pass(aOffH, bOffH);
    run_pass(aOffH, bOffL);
    run_pass(aOffL, bOffH);
    wout(KV ? g_k : g_q);

    if (KV) {
        __syncthreads();
        {
            const __nv_bfloat16* wh = g_wv_hi + (size_t)r * OUT_DIM * KD;
            const __nv_bfloat16* wl = g_wv_lo + (size_t)r * OUT_DIM * KD;
            for (int idx = tid; idx < 128 * U; idx += 512) {
                int n = idx / U, u = idx - n * U;
                *(uint4*)((char*)bH + n * SAB + u * 16) = ((const uint4*)(wh + (size_t)n * KD))[u];
                *(uint4*)((char*)bL + n * SAB + u * 16) = ((const uint4*)(wl + (size_t)n * KD))[u];
            }
        }
        __syncthreads();
#pragma unroll
        for (int j = 0; j < 8; j++)
#pragma unroll
            for (int b = 0; b < 4; b++) acc[j][b] = 0.f;
        run_pass(aOffH, bOffH);
        run_pass(aOffH, bOffL);
        run_pass(aOffL, bOffH);
        wout(g_v);
    }
}

// ---------------- attention logits + segment max ----------------
__global__ void k_attn_a(const int* __restrict__ dst_idx, int E)
{
    int t = blockIdx.x * blockDim.x + threadIdx.x;
    int e = t >> 3;
    int h = t & 7;
    if (e >= E) return;
    const float4* qp = (const float4*)&g_q[(size_t)e * OUT_DIM + h * HS];
    const float4* kp = (const float4*)&g_k[(size_t)e * OUT_DIM + h * HS];
    float a = 0.f;
#pragma unroll
    for (int i = 0; i < 4; i++) {
        float4 qv = qp[i], kv = kp[i];
        a += qv.x * kv.x + qv.y * kv.y + qv.z * kv.z + qv.w * kv.w;
    }
    a *= 0.08838834764831845f;  // 1/sqrt(128)
    g_a[(size_t)e * H_HEADS + h] = a;
    atomicMax(&g_amax[(size_t)dst_idx[e] * H_HEADS + h], fkey(a));
}

// ---------------- exp + segment denom ----------------
__global__ void k_attn_ex(const int* __restrict__ dst_idx, int E)
{
    int t = blockIdx.x * blockDim.x + threadIdx.x;
    int e = t >> 3;
    int h = t & 7;
    if (e >= E) return;
    int d = dst_idx[e];
    float am = finv(g_amax[(size_t)d * H_HEADS + h]);
    float ex = __expf(g_a[(size_t)e * H_HEADS + h] - am);
    g_ex[(size_t)e * H_HEADS + h] = ex;
    atomicAdd(&g_denom[(size_t)d * H_HEADS + h], ex);
}

// ---------------- weighted-V aggregation: dst-sorted, no atomics --------
__global__ void k_agg2(int M)
{
    int warp = (blockIdx.x * blockDim.x + threadIdx.x) >> 5;
    int lane = threadIdx.x & 31;
    if (warp >= M) return;
    const int m = warp;
    const int beg = g_doff[m];
    const int cnt = g_dhist[m];
    const int c0 = lane * 4;
    const int h = lane >> 2;
    float inv = 0.f;
    if (cnt > 0) inv = 1.f / g_denom[(size_t)m * H_HEADS + h];
    float4 acc = make_float4(0.f, 0.f, 0.f, 0.f);
    for (int i = 0; i < cnt; i++) {
        int e = g_dorder[beg + i];
        float alpha = g_ex[(size_t)e * H_HEADS + h] * inv;
        float4 v = *(const float4*)&g_v[(size_t)e * OUT_DIM + c0];
        acc.x += v.x * alpha;
        acc.y += v.y * alpha;
        acc.z += v.z * alpha;
        acc.w += v.w * alpha;
    }
    *(float4*)&g_hacc[(size_t)m * OUT_DIM + c0] = acc;
}

// ---------------- typed output projection (tiled by ntype) -------------
__global__ void __launch_bounds__(256, 2)
k_out_t(const float* __restrict__ Wa,
        const float* __restrict__ h_bias,
        const float* __restrict__ skip,
        const float* __restrict__ src_h,
        float* __restrict__ out, int M)
{
    const int r = blockIdx.y;
    const int cnt = g_ncur[r];
    const int tbase = blockIdx.x * TILE_M;
    if (tbase >= cnt) return;
    const size_t base = (size_t)r * M_MAX + tbase;
    const int ne = min(TILE_M, cnt - tbase);

    extern __shared__ float smf[];
    float* Ws = smf;
    float* Ds = smf + OUT_DIM * OUT_DIM;
    const int DS = TILE_M + 4;
    __shared__ int no[TILE_M];

    const int tid = threadIdx.x;
    if (tid < TILE_M) no[tid] = (tid < ne) ? g_norder[base + tid] : 0;
    __syncthreads();

    {
        const float* W = Wa + (size_t)r * OUT_DIM * OUT_DIM;
        for (int idx = tid; idx < OUT_DIM * (OUT_DIM / 4); idx += 256)
            ((float4*)Ws)[idx] = ((const float4*)W)[idx];
    }
    for (int idx = tid; idx < TILE_M * OUT_DIM; idx += 256) {
        int m = idx >> 7;
        int i = idx & 127;
        Ds[i * DS + m] = (m < ne) ?
            g_hacc[(size_t)no[m] * OUT_DIM + i] + h_bias[(size_t)r * OUT_DIM + i] : 0.f;
    }
    __syncthreads();

    const int c0 = (tid & 31) * 4;
    const int m0 = (tid >> 5) * 8;
    ull acc[4][4];
#pragma unroll
    for (int p = 0; p < 4; p++)
#pragma unroll
        for (int b = 0; b < 4; b++) acc[p][b] = 0ull;

#pragma unroll 8
    for (int i = 0; i < OUT_DIM; i++) {
        float4 w = *(const float4*)&Ws[i * OUT_DIM + c0];
        ull wd0 = dup2(w.x), wd1 = dup2(w.y), wd2 = dup2(w.z), wd3 = dup2(w.w);
        ulonglong2 p0 = *(const ulonglong2*)&Ds[i * DS + m0];
        ulonglong2 p1 = *(const ulonglong2*)&Ds[i * DS + m0 + 4];
        ull de[4] = {p0.x, p0.y, p1.x, p1.y};
#pragma unroll
        for (int p = 0; p < 4; p++) {
            acc[p][0] = fma2(de[p], wd0, acc[p][0]);
            acc[p][1] = fma2(de[p], wd1, acc[p][1]);
            acc[p][2] = fma2(de[p], wd2, acc[p][2]);
            acc[p][3] = fma2(de[p], wd3, acc[p][3]);
        }
    }

    float gate = 1.f / (1.f + __expf(-skip[r]));
    float og = 1.f - gate;
#pragma unroll
    for (int p = 0; p < 4; p++) {
        float2 v0 = unpk(acc[p][0]);
        float2 v1 = unpk(acc[p][1]);
        float2 v2 = unpk(acc[p][2]);
        float2 v3 = unpk(acc[p][3]);
        int mA = m0 + 2 * p, mB = mA + 1;
        if (mA < ne) {
            size_t gm = (size_t)no[mA] * OUT_DIM + c0;
            float4 s = *(const float4*)&src_h[gm];
            *(float4*)&out[gm] = make_float4(v0.x * gate + s.x * og,
                                             v1.x * gate + s.y * og,
                                             v2.x * gate + s.z * og,
                                             v3.x * gate + s.w * og);
        }
        if (mB < ne) {
            size_t gm = (size_t)no[mB] * OUT_DIM + c0;
            float4 s = *(const float4*)&src_h[gm];
            *(float4*)&out[gm] = make_float4(v0.y * gate + s.x * og,
                                             v1.y * gate + s.y * og,
                                             v2.y * gate + s.z * og,
                                             v3.y * gate + s.w * og);
        }
    }
}

// ---------------- launch ----------------
extern "C" void kernel_launch(void* const* d_in, const int* in_sizes, int n_in,
                              void* d_out, int out_size)
{
    const float* src_h  = (const float*)d_in[0];
    const float* src_tw = (const float*)d_in[1];
    const float* src_tb = (const float*)d_in[2];
    const float* edge_h = (const float*)d_in[3];
    const float* date   = (const float*)d_in[4];
    const int*   src_idx = (const int*)d_in[5];
    const int*   dst_idx = (const int*)d_in[6];
    const int*   etype   = (const int*)d_in[7];
    const int*   ntype   = (const int*)d_in[8];
    const float* Wq = (const float*)d_in[9];
    const float* Wk = (const float*)d_in[10];
    const float* Wv = (const float*)d_in[11];
    const float* Wa = (const float*)d_in[12];
    const float* h_bias = (const float*)d_in[13];
    const float* skip   = (const float*)d_in[14];
    const float* sg = (const float*)d_in[15];
    const float* sb = (const float*)d_in[16];
    const float* dg = (const float*)d_in[17];
    const float* db = (const float*)d_in[18];
    float* out = (float*)d_out;

    const int E = in_sizes[4];
    const int M = in_sizes[8];

    const int SMQ  = 4 * 128 * (IN_DIM + 8) * 2;    // 139264
    const int SMKV = 4 * 128 * (CAT_DIM + 8) * 2;   // 172032
    const int SMO  = (OUT_DIM * OUT_DIM + OUT_DIM * (TILE_M + 4)) * 4;
    cudaFuncSetAttribute(k_pm<IN_DIM, false>, cudaFuncAttributeMaxDynamicSharedMemorySize, SMQ);
    cudaFuncSetAttribute(k_pm<CAT_DIM, true>, cudaFuncAttributeMaxDynamicSharedMemorySize, SMKV);
    cudaFuncSetAttribute(k_out_t, cudaFuncAttributeMaxDynamicSharedMemorySize, SMO);

    int mx = (E > M) ? E : M;
    k_reset<<<(M * H_HEADS + 255) / 256, 256>>>(M);
    k_scatter_all<<<(mx + 255) / 256, 256>>>(etype, ntype, dst_idx, E, M);
    k_scan_dst<<<1, 1024>>>(M);
    k_scatter_dst<<<(E + 255) / 256, 256>>>(dst_idx, E);
    {
        dim3 gw((CAT_DIM / 32) * (OUT_DIM / 32), R_TYPES, 3);
        k_wconv2<<<gw, dim3(32, 8)>>>(Wq, Wk, Wv);
    }
    k_dia<<<(E * 32 + 255) / 256, 256>>>(src_h, src_tw, src_tb, edge_h, date,
                                         src_idx, dst_idx, sg, sb, dg, db, E);
    dim3 gq((E + TILE_E - 1) / TILE_E, R_TYPES);
    k_pm<IN_DIM,  false><<<gq, 512, SMQ >>>();
    k_pm<CAT_DIM, true ><<<gq, 512, SMKV>>>();
    k_attn_a <<<(E * H_HEADS + 255) / 256, 256>>>(dst_idx, E);
    k_attn_ex<<<(E * H_HEADS + 255) / 256, 256>>>(dst_idx, E);
    k_agg2<<<(M * 32 + 255) / 256, 256>>>(M);
    dim3 go((M + TILE_M - 1) / TILE_M, T_TYPES);
    k_out_t<<<go, 256, SMO>>>(Wa, h_bias, skip, src_h, out, M);
}